// round 1
// baseline (speedup 1.0000x reference)
#include <cuda_runtime.h>
#include <math.h>

// Problem constants (fixed shapes for this problem)
#define NPG     100     // nodes per graph
#define EPG     1600    // edges per graph
#define NH      64      // hidden width
#define NINP    3
#define H2      32
#define NOUT    10
#define KCHEB   5
#define STRIDE  68      // feature row stride in floats (16B aligned, bank-friendly)
#define NTHREADS 256

// ---------------- shared memory layout (dynamic) ----------------
// bufA   : NPG*STRIDE floats            (6800)
// bufB   : NPG*STRIDE floats            (6800)
// Wbuf   : 64*64 floats                 (4096)
// coef_s : EPG floats                   (1600)
// col_s  : EPG u16
// rowptr : 104 ints
// cnt    : 104 ints
// dis    : 100 floats
// gv     : 64 floats
// hv     : 32 floats
// zv     : 16 floats
struct SmemLayout {
    static constexpr int bufA_off   = 0;
    static constexpr int bufB_off   = NPG * STRIDE;                 // floats
    static constexpr int Wbuf_off   = bufB_off + NPG * STRIDE;
    static constexpr int coef_off   = Wbuf_off + 64 * 64;
    static constexpr int floats_end = coef_off + EPG;
    // bytes after the float region:
    static constexpr int col_bytes  = EPG * 2;
    static constexpr int total_bytes =
        floats_end * 4 + col_bytes + 104*4 + 104*4 + 100*4 + 64*4 + 32*4 + 16*4 + 64;
};

// ---------------- Lhat via per-graph CSR gather ----------------
// dst[i][j] = cheb ? 2*(cl*src[i][j] + sum_e coef*src[col][j]) - dst[i][j]
//                  :    cl*src[i][j] + sum_e coef*src[col][j]
__device__ __forceinline__ void lhat64(
    float* dst, const float* src, bool cheb,
    const float* coef_s, const unsigned short* col_s, const int* rowptr,
    float cl, int tid)
{
    const int j  = tid & 31;
    const int rg = tid >> 5;           // 8 rows per pass
    for (int base = 0; base < NPG; base += 8) {
        int i = base + rg;
        if (i < NPG) {
            const float* srow = src + i * STRIDE;
            float a0 = cl * srow[j];
            float a1 = cl * srow[j + 32];
            const int e1 = rowptr[i + 1];
            for (int e = rowptr[i]; e < e1; e++) {
                float c = coef_s[e];
                const float* sc = src + (int)col_s[e] * STRIDE;
                a0 = fmaf(c, sc[j],      a0);
                a1 = fmaf(c, sc[j + 32], a1);
            }
            float* drow = dst + i * STRIDE;
            if (cheb) {
                drow[j]      = 2.0f * a0 - drow[j];
                drow[j + 32] = 2.0f * a1 - drow[j + 32];
            } else {
                drow[j]      = a0;
                drow[j + 32] = a1;
            }
        }
    }
    __syncthreads();
}

__device__ __forceinline__ void lhat3(
    float* dst, const float* src, bool cheb,
    const float* coef_s, const unsigned short* col_s, const int* rowptr,
    float cl, int tid)
{
    if (tid < NPG) {
        const int i = tid;
        const float* srow = src + i * STRIDE;
        float a0 = cl * srow[0];
        float a1 = cl * srow[1];
        float a2 = cl * srow[2];
        const int e1 = rowptr[i + 1];
        for (int e = rowptr[i]; e < e1; e++) {
            float c = coef_s[e];
            const float* sc = src + (int)col_s[e] * STRIDE;
            a0 = fmaf(c, sc[0], a0);
            a1 = fmaf(c, sc[1], a1);
            a2 = fmaf(c, sc[2], a2);
        }
        float* drow = dst + i * STRIDE;
        if (cheb) {
            drow[0] = 2.0f * a0 - drow[0];
            drow[1] = 2.0f * a1 - drow[1];
            drow[2] = 2.0f * a2 - drow[2];
        } else {
            drow[0] = a0; drow[1] = a1; drow[2] = a2;
        }
    }
    __syncthreads();
}

// ---------------- GEMM: acc[100x64] += Tx[100xCIN] @ W[CINx64] ----------------
// Thread tiling: tx = tid&15 owns cols 4*tx..4*tx+3 (float4), ty = tid>>4 owns
// rows ty + 16*r for r = 0..6 (row 96+ty only valid for ty<4).
template<int CIN>
__device__ __forceinline__ void gemm_acc(
    float (&acc)[7][4], const float* __restrict__ Tx,
    const float* __restrict__ Wg, float* Wbuf, int tid)
{
    for (int idx = tid; idx < CIN * 64; idx += NTHREADS) Wbuf[idx] = Wg[idx];
    __syncthreads();
    const int tx = tid & 15, ty = tid >> 4;
    if (CIN == 3) {
        #pragma unroll
        for (int kk = 0; kk < 3; kk++) {
            float4 w = *(const float4*)(Wbuf + kk * 64 + tx * 4);
            #pragma unroll
            for (int r = 0; r < 7; r++) {
                if (r < 6 || ty < 4) {
                    float t = Tx[(ty + 16 * r) * STRIDE + kk];
                    acc[r][0] = fmaf(t, w.x, acc[r][0]);
                    acc[r][1] = fmaf(t, w.y, acc[r][1]);
                    acc[r][2] = fmaf(t, w.z, acc[r][2]);
                    acc[r][3] = fmaf(t, w.w, acc[r][3]);
                }
            }
        }
    } else {
        #pragma unroll 2
        for (int kc = 0; kc < CIN / 4; kc++) {
            float w[4][4];
            #pragma unroll
            for (int q = 0; q < 4; q++) {
                float4 wv = *(const float4*)(Wbuf + (kc * 4 + q) * 64 + tx * 4);
                w[q][0] = wv.x; w[q][1] = wv.y; w[q][2] = wv.z; w[q][3] = wv.w;
            }
            #pragma unroll
            for (int r = 0; r < 7; r++) {
                if (r < 6 || ty < 4) {
                    float4 tv = *(const float4*)(Tx + (ty + 16 * r) * STRIDE + kc * 4);
                    float tf[4] = {tv.x, tv.y, tv.z, tv.w};
                    #pragma unroll
                    for (int q = 0; q < 4; q++)
                        #pragma unroll
                        for (int c = 0; c < 4; c++)
                            acc[r][c] = fmaf(tf[q], w[q][c], acc[r][c]);
                }
            }
        }
    }
    __syncthreads();
}

// ---------------- One ChebConv layer (+bias +ReLU), result -> bufA ----------------
template<int CIN>
__device__ __noinline__ void cheb_layer(
    float* bufA, float* bufB, float* Wbuf,
    const float* __restrict__ Wg, const float* __restrict__ bg,
    const float* coef_s, const unsigned short* col_s, const int* rowptr,
    float cl, int tid)
{
    float acc[7][4];
    #pragma unroll
    for (int r = 0; r < 7; r++)
        #pragma unroll
        for (int c = 0; c < 4; c++) acc[r][c] = 0.0f;

    // k = 0 : Tx0 = X (bufA)
    gemm_acc<CIN>(acc, bufA, Wg, Wbuf, tid);
    // k = 1 : Tx1 = Lhat(X) -> bufB
    if (CIN == 3) lhat3(bufB, bufA, false, coef_s, col_s, rowptr, cl, tid);
    else          lhat64(bufB, bufA, false, coef_s, col_s, rowptr, cl, tid);
    gemm_acc<CIN>(acc, bufB, Wg + 1 * CIN * 64, Wbuf, tid);
    // k = 2 : Tx2 = 2*Lhat(Tx1) - Tx0 -> bufA (in place)
    if (CIN == 3) lhat3(bufA, bufB, true, coef_s, col_s, rowptr, cl, tid);
    else          lhat64(bufA, bufB, true, coef_s, col_s, rowptr, cl, tid);
    gemm_acc<CIN>(acc, bufA, Wg + 2 * CIN * 64, Wbuf, tid);
    // k = 3
    if (CIN == 3) lhat3(bufB, bufA, true, coef_s, col_s, rowptr, cl, tid);
    else          lhat64(bufB, bufA, true, coef_s, col_s, rowptr, cl, tid);
    gemm_acc<CIN>(acc, bufB, Wg + 3 * CIN * 64, Wbuf, tid);
    // k = 4
    if (CIN == 3) lhat3(bufA, bufB, true, coef_s, col_s, rowptr, cl, tid);
    else          lhat64(bufA, bufB, true, coef_s, col_s, rowptr, cl, tid);
    gemm_acc<CIN>(acc, bufA, Wg + 4 * CIN * 64, Wbuf, tid);

    // h = relu(acc + b) -> bufA
    const int tx = tid & 15, ty = tid >> 4;
    float4 bb = *(const float4*)(bg + tx * 4);
    #pragma unroll
    for (int r = 0; r < 7; r++) {
        if (r < 6 || ty < 4) {
            float4 o;
            o.x = fmaxf(acc[r][0] + bb.x, 0.0f);
            o.y = fmaxf(acc[r][1] + bb.y, 0.0f);
            o.z = fmaxf(acc[r][2] + bb.z, 0.0f);
            o.w = fmaxf(acc[r][3] + bb.w, 0.0f);
            *(float4*)(bufA + (ty + 16 * r) * STRIDE + tx * 4) = o;
        }
    }
    __syncthreads();
}

// ---------------- main kernel: one CTA per graph ----------------
__global__ __launch_bounds__(NTHREADS, 2)
void chebnet_kernel(
    const float* __restrict__ x, const int* __restrict__ ei,
    const float* __restrict__ lambda_max,
    const float* __restrict__ W1, const float* __restrict__ b1,
    const float* __restrict__ W2, const float* __restrict__ b2,
    const float* __restrict__ W3, const float* __restrict__ b3,
    const float* __restrict__ bn_g, const float* __restrict__ bn_b,
    const float* __restrict__ bn_m, const float* __restrict__ bn_v,
    const float* __restrict__ fc1w, const float* __restrict__ fc1b,
    const float* __restrict__ fc2w, const float* __restrict__ fc2b,
    float* __restrict__ out, int E)
{
    extern __shared__ float smem_f[];
    float* bufA   = smem_f + SmemLayout::bufA_off;
    float* bufB   = smem_f + SmemLayout::bufB_off;
    float* Wbuf   = smem_f + SmemLayout::Wbuf_off;
    float* coef_s = smem_f + SmemLayout::coef_off;
    unsigned short* col_s = (unsigned short*)(smem_f + SmemLayout::floats_end);
    int*   rowptr = (int*)(col_s + EPG);
    int*   cnt    = rowptr + 104;
    float* dis    = (float*)(cnt + 104);
    float* gv     = dis + 100;
    float* hv     = gv + 64;
    float* zv     = hv + 32;

    const int g = blockIdx.x, tid = threadIdx.x;
    const int nbase = g * NPG, ebase = g * EPG;

    if (tid < NPG) cnt[tid] = 0;
    __syncthreads();

    // Pass 1: stage packed (src,dst) local edges in bufB, histogram per src row.
    int* stage = (int*)bufB;
    for (int e = tid; e < EPG; e += NTHREADS) {
        int s = ei[ebase + e] - nbase;
        int d = ei[E + ebase + e] - nbase;
        stage[e] = (s << 8) | d;
        atomicAdd(&cnt[s], 1);
    }
    // Load node features X into bufA (cols 0..2).
    for (int idx = tid; idx < NPG * NINP; idx += NTHREADS) {
        int i = idx / NINP, c = idx - i * NINP;
        bufA[i * STRIDE + c] = x[(nbase + i) * NINP + c];
    }
    __syncthreads();

    // degree -> dis, serial prefix for rowptr
    if (tid < NPG) {
        int dg = cnt[tid];
        dis[tid] = (dg > 0) ? rsqrtf((float)dg) : 0.0f;
    }
    if (tid == 0) {
        int run = 0;
        for (int i = 0; i < NPG; i++) { rowptr[i] = run; run += cnt[i]; }
        rowptr[NPG] = run;
    }
    __syncthreads();
    if (tid < NPG) cnt[tid] = rowptr[tid];
    const float lmx = lambda_max[g];
    const float s2  = 2.0f / lmx;
    const float cl  = s2 - 1.0f;
    __syncthreads();

    // Pass 2: CSR fill (coef + dst), positions via shared atomic counters.
    for (int e = tid; e < EPG; e += NTHREADS) {
        int pk = stage[e];
        int s = pk >> 8, d = pk & 255;
        int pos = atomicAdd(&cnt[s], 1);
        col_s[pos]  = (unsigned short)d;
        coef_s[pos] = -s2 * dis[s] * dis[d];
    }
    __syncthreads();

    // 3 ChebConv layers
    cheb_layer<NINP>(bufA, bufB, Wbuf, W1, b1, coef_s, col_s, rowptr, cl, tid);
    cheb_layer<NH>  (bufA, bufB, Wbuf, W2, b2, coef_s, col_s, rowptr, cl, tid);
    cheb_layer<NH>  (bufA, bufB, Wbuf, W3, b3, coef_s, col_s, rowptr, cl, tid);

    // mean pool over 100 nodes + BatchNorm (eval)
    if (tid < NH) {
        float s = 0.0f;
        for (int i = 0; i < NPG; i++) s += bufA[i * STRIDE + tid];
        float gm = s * (1.0f / (float)NPG);
        gv[tid] = (gm - bn_m[tid]) * rsqrtf(bn_v[tid] + 1e-5f) * bn_g[tid] + bn_b[tid];
    }
    __syncthreads();
    // fc1 + relu
    if (tid < H2) {
        float a = fc1b[tid];
        for (int j = 0; j < NH; j++) a = fmaf(gv[j], fc1w[j * H2 + tid], a);
        hv[tid] = fmaxf(a, 0.0f);
    }
    __syncthreads();
    // fc2
    if (tid < NOUT) {
        float a = fc2b[tid];
        for (int m = 0; m < H2; m++) a = fmaf(hv[m], fc2w[m * NOUT + tid], a);
        zv[tid] = a;
    }
    __syncthreads();
    // log_softmax + write
    if (tid == 0) {
        float mx = zv[0];
        #pragma unroll
        for (int c = 1; c < NOUT; c++) mx = fmaxf(mx, zv[c]);
        float se = 0.0f;
        #pragma unroll
        for (int c = 0; c < NOUT; c++) se += expf(zv[c] - mx);
        float lse = mx + logf(se);
        #pragma unroll
        for (int c = 0; c < NOUT; c++) out[g * NOUT + c] = zv[c] - lse;
    }
}

extern "C" void kernel_launch(void* const* d_in, const int* in_sizes, int n_in,
                              void* d_out, int out_size)
{
    const float* x    = (const float*)d_in[0];
    const int*   ei   = (const int*)  d_in[1];
    // d_in[2] = batch (unused; graphs are contiguous blocks of NPG nodes)
    const float* lmax = (const float*)d_in[3];
    const float* W1   = (const float*)d_in[4];
    const float* b1   = (const float*)d_in[5];
    const float* W2   = (const float*)d_in[6];
    const float* b2   = (const float*)d_in[7];
    const float* W3   = (const float*)d_in[8];
    const float* b3   = (const float*)d_in[9];
    const float* bn_g = (const float*)d_in[10];
    const float* bn_b = (const float*)d_in[11];
    const float* bn_m = (const float*)d_in[12];
    const float* bn_v = (const float*)d_in[13];
    const float* fc1w = (const float*)d_in[14];
    const float* fc1b = (const float*)d_in[15];
    const float* fc2w = (const float*)d_in[16];
    const float* fc2b = (const float*)d_in[17];
    float* out = (float*)d_out;

    const int E = in_sizes[1] / 2;       // 1,600,000
    const int G = in_sizes[3];           // 1,000

    const int smem_bytes = SmemLayout::total_bytes;
    cudaFuncSetAttribute(chebnet_kernel,
                         cudaFuncAttributeMaxDynamicSharedMemorySize, smem_bytes);

    chebnet_kernel<<<G, NTHREADS, smem_bytes>>>(
        x, ei, lmax, W1, b1, W2, b2, W3, b3,
        bn_g, bn_b, bn_m, bn_v, fc1w, fc1b, fc2w, fc2b, out, E);
}